// round 6
// baseline (speedup 1.0000x reference)
#include <cuda_runtime.h>
#include <cuda_bf16.h>
#include <cstdint>

// Problem constants
#define BB   2
#define SS   2048
#define EE   1024
#define HH   16
#define HKV  4
#define DD   64
#define KVE  (HKV * DD)   // 256
#define MM   (BB * SS)    // 4096

// Scratch (allocation-free rule: __device__ globals)
__device__ float g_Q[(size_t)MM * EE];
__device__ float g_K[(size_t)MM * KVE];
__device__ float g_V[(size_t)MM * KVE];
__device__ float g_C[(size_t)MM * EE];

__device__ __forceinline__ uint32_t f2tf32(float x) {
    uint32_t u;
    asm("cvt.rna.tf32.f32 %0, %1;" : "=r"(u) : "f"(x));
    return u;
}
__device__ __forceinline__ void mma_tf32(float* c, const uint32_t* a,
                                         const uint32_t* b) {
    asm volatile(
        "mma.sync.aligned.m16n8k8.row.col.f32.tf32.tf32.f32 "
        "{%0,%1,%2,%3}, {%4,%5,%6,%7}, {%8,%9}, {%0,%1,%2,%3};"
        : "+f"(c[0]), "+f"(c[1]), "+f"(c[2]), "+f"(c[3])
        : "r"(a[0]), "r"(a[1]), "r"(a[2]), "r"(a[3]),
          "r"(b[0]), "r"(b[1]));
}
__device__ __forceinline__ void cp16(uint32_t d, const void* s) {
    asm volatile("cp.async.cg.shared.global [%0], [%1], 16;"
                 :: "r"(d), "l"(s) : "memory");
}
__device__ __forceinline__ void cp_commit() {
    asm volatile("cp.async.commit_group;" ::: "memory");
}
__device__ __forceinline__ void cp_wait0() {
    asm volatile("cp.async.wait_group 0;" ::: "memory");
}
__device__ __forceinline__ void cp_wait1() {
    asm volatile("cp.async.wait_group 1;" ::: "memory");
}
__device__ __forceinline__ uint32_t cvta_s(const void* p) {
    return (uint32_t)__cvta_generic_to_shared(p);
}

// ===========================================================================
// tf32 tensor-core GEMM core: 3-stage cp.async ring, ONE barrier per k-iter.
// Loop order: wait -> sync -> prefetch(it+2) -> compute(it).
// The sync both publishes tile `it` to all warps and proves tile `it-1`'s
// readers are done, so overwriting buffer (it+2)%3 == (it-1)%3 is safe.
// ===========================================================================
#define GBK   32
#define GLDA  36
#define GBUF  (128 * GLDA)              // floats per buffer
#define GSTG  3
#define GSMEM (2 * GSTG * GBUF * 4)     // 110592 bytes

__device__ __forceinline__ void gemm_core(
    const float* __restrict__ A, const float* __restrict__ W,
    const float* __restrict__ bias, float* __restrict__ C,
    int Nc, int row0)
{
    extern __shared__ float sm[];
    float* As = sm;                     // [GSTG][GBUF]
    float* Bs = sm + GSTG * GBUF;       // [GSTG][GBUF]

    const int tid  = threadIdx.x;
    const int K    = EE;

    const int r    = tid >> 1;
    const int ksub = (tid & 1) * 16;
    const float* Ag = A + (size_t)(row0 + r) * K + ksub;
    const float* Wg = W + (size_t)r * K + ksub;
    const uint32_t Asd = cvta_s(As + r * GLDA + ksub);
    const uint32_t Bsd = cvta_s(Bs + r * GLDA + ksub);

    const int lane = tid & 31;
    const int wid  = tid >> 5;
    const int wm   = (wid & 1) * 64;
    const int wn   = (wid >> 1) * 32;
    const int g    = lane >> 2;
    const int tig  = lane & 3;

    float acc[4][4][4];
#pragma unroll
    for (int mt = 0; mt < 4; mt++)
#pragma unroll
        for (int nt = 0; nt < 4; nt++)
#pragma unroll
            for (int i = 0; i < 4; i++) acc[mt][nt][i] = 0.f;

    // prologue: stage k-chunks 0 and 1 into buffers 0 and 1
#pragma unroll
    for (int s = 0; s < 2; s++) {
#pragma unroll
        for (int i = 0; i < 4; i++) {
            cp16(Asd + s * GBUF * 4 + i * 16, Ag + s * GBK + i * 4);
            cp16(Bsd + s * GBUF * 4 + i * 16, Wg + s * GBK + i * 4);
        }
        cp_commit();
    }

    const int NI = K / GBK;             // 32
    int bcur = 0, bpre = 2;             // compute buffer, prefetch buffer
    for (int it = 0; it < NI; it++) {
        if (it + 1 < NI) cp_wait1(); else cp_wait0();
        __syncthreads();

        if (it + 2 < NI) {
            const float* a = Ag + (it + 2) * GBK;
            const float* w = Wg + (it + 2) * GBK;
            const uint32_t ad = Asd + bpre * GBUF * 4;
            const uint32_t bd = Bsd + bpre * GBUF * 4;
#pragma unroll
            for (int i = 0; i < 4; i++) {
                cp16(ad + i * 16, a + i * 4);
                cp16(bd + i * 16, w + i * 4);
            }
            cp_commit();
        }

        const float* Ab = As + bcur * GBUF;
        const float* Bb = Bs + bcur * GBUF;
#pragma unroll
        for (int ks = 0; ks < 4; ks++) {
            uint32_t a[4][4], b[4][2];
#pragma unroll
            for (int mt = 0; mt < 4; mt++) {
                const float* ap = Ab + (wm + mt * 16 + g) * GLDA + ks * 8 + tig;
                a[mt][0] = f2tf32(ap[0]);
                a[mt][1] = f2tf32(ap[8 * GLDA]);
                a[mt][2] = f2tf32(ap[4]);
                a[mt][3] = f2tf32(ap[8 * GLDA + 4]);
            }
#pragma unroll
            for (int nt = 0; nt < 4; nt++) {
                const float* bp = Bb + (wn + nt * 8 + g) * GLDA + ks * 8 + tig;
                b[nt][0] = f2tf32(bp[0]);
                b[nt][1] = f2tf32(bp[4]);
            }
#pragma unroll
            for (int mt = 0; mt < 4; mt++)
#pragma unroll
                for (int nt = 0; nt < 4; nt++)
                    mma_tf32(acc[mt][nt], a[mt], b[nt]);
        }

        bcur = (bcur + 1 == GSTG) ? 0 : bcur + 1;
        bpre = (bpre + 1 == GSTG) ? 0 : bpre + 1;
    }

    // epilogue: fused bias, direct stores
#pragma unroll
    for (int mt = 0; mt < 4; mt++) {
        const int rowa = row0 + wm + mt * 16 + g;
#pragma unroll
        for (int nt = 0; nt < 4; nt++) {
            const int cola = wn + nt * 8 + 2 * tig;
            const float2 bv = *(const float2*)(bias + cola);
            float2 v0, v1;
            v0.x = acc[mt][nt][0] + bv.x;
            v0.y = acc[mt][nt][1] + bv.y;
            v1.x = acc[mt][nt][2] + bv.x;
            v1.y = acc[mt][nt][3] + bv.y;
            *(float2*)(C + (size_t)rowa * Nc + cola)       = v0;
            *(float2*)(C + (size_t)(rowa + 8) * Nc + cola) = v1;
        }
    }
}

// fused Q/K/V projection: tiles 0-7 -> Q, 8-9 -> K, 10-11 -> V
__global__ void __launch_bounds__(256, 2)
gemm_qkv(const float* __restrict__ x,
         const float* __restrict__ wq, const float* __restrict__ bq, float* Qo,
         const float* __restrict__ wk, const float* __restrict__ bk, float* Ko,
         const float* __restrict__ wv, const float* __restrict__ bv, float* Vo)
{
    const int bx   = blockIdx.x;
    const int row0 = blockIdx.y * 128;
    const float *W, *bias;
    float* C;
    int Nc, c0;
    if (bx < 8)       { W = wq; bias = bq; C = Qo; Nc = EE;  c0 = bx * 128; }
    else if (bx < 10) { W = wk; bias = bk; C = Ko; Nc = KVE; c0 = (bx - 8) * 128; }
    else              { W = wv; bias = bv; C = Vo; Nc = KVE; c0 = (bx - 10) * 128; }
    gemm_core(x, W + (size_t)c0 * EE, bias + c0, C + c0, Nc, row0);
}

__global__ void __launch_bounds__(256, 2)
gemm_single(const float* __restrict__ A, const float* __restrict__ W,
            const float* __restrict__ bias, float* __restrict__ C)
{
    const int c0 = blockIdx.x * 128;
    gemm_core(A, W + (size_t)c0 * EE, bias + c0, C + c0, EE, blockIdx.y * 128);
}

// ===========================================================================
// Tensor-core flash attention (causal, GQA), tf32 mma.sync.
// 2-stage cp.async K/V ring, ONE barrier per KV tile:
//   wait0 -> sync -> prefetch(t+1) -> compute(t).
// ===========================================================================
#define PLD 68
#define KLD 68
#define VLD 72
#define FKB (64 * KLD)
#define FVB (64 * VLD)
#define FSMEM ((128 * PLD + 2 * FKB + 2 * FVB) * 4)   // 106496 bytes

__global__ void __launch_bounds__(256, 2)
flash_tc(const float* __restrict__ Q, const float* __restrict__ K,
         const float* __restrict__ V, float* __restrict__ O)
{
    extern __shared__ float fsm[];
    float* Ps = fsm;                 // [128][PLD]: Q raw fp32, then P tf32 bits
    float* Kb = fsm + 128 * PLD;     // [2][64][KLD] raw fp32
    float* Vb = Kb + 2 * FKB;        // [2][64][VLD] raw fp32

    const int tid  = threadIdx.x;
    const int lane = tid & 31;
    const int wid  = tid >> 5;
    const int g    = lane >> 2;
    const int tig  = lane & 3;
    const int m0   = (gridDim.x - 1 - blockIdx.x) * 128;   // heavy-first
    const int h    = blockIdx.y;
    const int b    = blockIdx.z;
    const int kvh  = h >> 2;

    const int sr  = tid >> 2;
    const int sc4 = (tid & 3) * 16;
    const float* kgb = K + ((size_t)(b * SS + sr)) * KVE + kvh * DD + sc4;
    const float* vgb = V + ((size_t)(b * SS + sr)) * KVE + kvh * DD + sc4;
    const uint32_t kd0 = cvta_s(Kb + sr * KLD + sc4);
    const uint32_t vd0 = cvta_s(Vb + sr * VLD + sc4);

    // stage Q (scaled by 1/8, raw fp32)
    {
        const int r  = tid >> 1;
        const int c0 = (tid & 1) * 32;
        const float* qg = Q + ((size_t)(b * SS + m0 + r)) * EE + h * DD + c0;
        float* dst = Ps + r * PLD + c0;
#pragma unroll
        for (int i = 0; i < 8; i++) {
            float4 v = *(const float4*)(qg + i * 4);
            dst[i * 4 + 0] = v.x * 0.125f;
            dst[i * 4 + 1] = v.y * 0.125f;
            dst[i * 4 + 2] = v.z * 0.125f;
            dst[i * 4 + 3] = v.w * 0.125f;
        }
    }

    const int ntile = m0 / 64 + 2;

    // prologue: stage KV tile 0 into buffer 0
#pragma unroll
    for (int i = 0; i < 4; i++) {
        cp16(kd0 + i * 16, kgb + i * 4);
        cp16(vd0 + i * 16, vgb + i * 4);
    }
    cp_commit();
    __syncthreads();                 // Q visible

    uint32_t qa[8][4];
    {
        const float* base = Ps + (wid * 16 + g) * PLD;
#pragma unroll
        for (int ks = 0; ks < 8; ks++) {
            qa[ks][0] = f2tf32(base[ks * 8 + tig]);
            qa[ks][1] = f2tf32(base[8 * PLD + ks * 8 + tig]);
            qa[ks][2] = f2tf32(base[ks * 8 + tig + 4]);
            qa[ks][3] = f2tf32(base[8 * PLD + ks * 8 + tig + 4]);
        }
    }

    float oacc[8][4];
#pragma unroll
    for (int nt = 0; nt < 8; nt++)
#pragma unroll
        for (int i = 0; i < 4; i++) oacc[nt][i] = 0.f;
    float mrow[2] = { -1e30f, -1e30f };
    float lrow[2] = { 0.f, 0.f };

    const int r0 = m0 + wid * 16 + g;

    for (int t = 0; t < ntile; t++) {
        const int cb = t & 1;

        cp_wait0();
        __syncthreads();             // tile t visible; tile t-1 fully consumed

        if (t + 1 < ntile) {         // prefetch into buffer 1-cb (safe now)
            const float* kg = kgb + (size_t)((t + 1) * 64) * KVE;
            const float* vg = vgb + (size_t)((t + 1) * 64) * KVE;
            const uint32_t kd = kd0 + (1 - cb) * FKB * 4;
            const uint32_t vd = vd0 + (1 - cb) * FVB * 4;
#pragma unroll
            for (int i = 0; i < 4; i++) {
                cp16(kd + i * 16, kg + i * 4);
                cp16(vd + i * 16, vg + i * 4);
            }
            cp_commit();
        }

        const int j0 = t * 64;
        const bool active = (j0 <= m0 + wid * 16 + 15);    // warp-uniform
        if (active) {
            const float* Kc = Kb + cb * FKB;
            const float* Vc = Vb + cb * FVB;

            // S = Q @ K^T
            float sc[8][4];
#pragma unroll
            for (int nt = 0; nt < 8; nt++)
#pragma unroll
                for (int i = 0; i < 4; i++) sc[nt][i] = 0.f;
#pragma unroll
            for (int ks = 0; ks < 8; ks++)
#pragma unroll
                for (int nt = 0; nt < 8; nt++) {
                    uint32_t bb[2];
                    const float* bp = Kc + (nt * 8 + g) * KLD + ks * 8 + tig;
                    bb[0] = f2tf32(bp[0]);
                    bb[1] = f2tf32(bp[4]);
                    mma_tf32(sc[nt], qa[ks], bb);
                }

            // causal mask (diagonal tiles only)
            if (j0 + 63 > r0) {
#pragma unroll
                for (int nt = 0; nt < 8; nt++) {
                    const int c = j0 + nt * 8 + 2 * tig;
                    if (c     > r0)     sc[nt][0] = -1e30f;
                    if (c + 1 > r0)     sc[nt][1] = -1e30f;
                    if (c     > r0 + 8) sc[nt][2] = -1e30f;
                    if (c + 1 > r0 + 8) sc[nt][3] = -1e30f;
                }
            }

            // row max (quad reduce)
            float tm0 = -1e30f, tm1 = -1e30f;
#pragma unroll
            for (int nt = 0; nt < 8; nt++) {
                tm0 = fmaxf(tm0, fmaxf(sc[nt][0], sc[nt][1]));
                tm1 = fmaxf(tm1, fmaxf(sc[nt][2], sc[nt][3]));
            }
            tm0 = fmaxf(tm0, __shfl_xor_sync(0xffffffffu, tm0, 1));
            tm0 = fmaxf(tm0, __shfl_xor_sync(0xffffffffu, tm0, 2));
            tm1 = fmaxf(tm1, __shfl_xor_sync(0xffffffffu, tm1, 1));
            tm1 = fmaxf(tm1, __shfl_xor_sync(0xffffffffu, tm1, 2));

            const float mn0 = fmaxf(mrow[0], tm0);
            const float mn1 = fmaxf(mrow[1], tm1);
            const float cr0 = __expf(mrow[0] - mn0);
            const float cr1 = __expf(mrow[1] - mn1);
            mrow[0] = mn0; mrow[1] = mn1;

            float ls0 = 0.f, ls1 = 0.f;
#pragma unroll
            for (int nt = 0; nt < 8; nt++) {
                sc[nt][0] = __expf(sc[nt][0] - mn0); ls0 += sc[nt][0];
                sc[nt][1] = __expf(sc[nt][1] - mn0); ls0 += sc[nt][1];
                sc[nt][2] = __expf(sc[nt][2] - mn1); ls1 += sc[nt][2];
                sc[nt][3] = __expf(sc[nt][3] - mn1); ls1 += sc[nt][3];
            }
            lrow[0] = lrow[0] * cr0 + ls0;
            lrow[1] = lrow[1] * cr1 + ls1;
#pragma unroll
            for (int nt = 0; nt < 8; nt++) {
                oacc[nt][0] *= cr0; oacc[nt][1] *= cr0;
                oacc[nt][2] *= cr1; oacc[nt][3] *= cr1;
            }

            // P -> smem (tf32 bits), warp-private rows
            uint32_t* pr = (uint32_t*)(Ps + (wid * 16 + g) * PLD);
#pragma unroll
            for (int nt = 0; nt < 8; nt++) {
                uint2 w0, w1;
                w0.x = f2tf32(sc[nt][0]); w0.y = f2tf32(sc[nt][1]);
                w1.x = f2tf32(sc[nt][2]); w1.y = f2tf32(sc[nt][3]);
                *(uint2*)(pr + nt * 8 + 2 * tig)           = w0;
                *(uint2*)(pr + 8 * PLD + nt * 8 + 2 * tig) = w1;
            }
            __syncwarp();

            // O += P @ V
#pragma unroll
            for (int ks = 0; ks < 8; ks++) {
                uint32_t pa[4];
                pa[0] = pr[ks * 8 + tig];
                pa[1] = pr[8 * PLD + ks * 8 + tig];
                pa[2] = pr[ks * 8 + tig + 4];
                pa[3] = pr[8 * PLD + ks * 8 + tig + 4];
#pragma unroll
                for (int nt = 0; nt < 8; nt++) {
                    uint32_t bb[2];
                    bb[0] = f2tf32(Vc[(ks * 8 + tig) * VLD + nt * 8 + g]);
                    bb[1] = f2tf32(Vc[(ks * 8 + tig + 4) * VLD + nt * 8 + g]);
                    mma_tf32(oacc[nt], pa, bb);
                }
            }
        }
    }

    // finalize
    lrow[0] += __shfl_xor_sync(0xffffffffu, lrow[0], 1);
    lrow[0] += __shfl_xor_sync(0xffffffffu, lrow[0], 2);
    lrow[1] += __shfl_xor_sync(0xffffffffu, lrow[1], 1);
    lrow[1] += __shfl_xor_sync(0xffffffffu, lrow[1], 2);
    const float inv0 = 1.f / lrow[0];
    const float inv1 = 1.f / lrow[1];

    float* og = O + ((size_t)(b * SS + r0)) * EE + h * DD;
#pragma unroll
    for (int nt = 0; nt < 8; nt++) {
        float2 v0, v1;
        v0.x = oacc[nt][0] * inv0; v0.y = oacc[nt][1] * inv0;
        v1.x = oacc[nt][2] * inv1; v1.y = oacc[nt][3] * inv1;
        *(float2*)(og + nt * 8 + 2 * tig)                  = v0;
        *(float2*)(og + (size_t)8 * EE + nt * 8 + 2 * tig) = v1;
    }
}

// ---------------------------------------------------------------------------
// Launch
// ---------------------------------------------------------------------------
extern "C" void kernel_launch(void* const* d_in, const int* in_sizes, int n_in,
                              void* d_out, int out_size)
{
    const float* x    = (const float*)d_in[0];
    // d_in[1] is the causal mask (triu, k=1) — applied analytically (j<=i).
    const float* wq_w = (const float*)d_in[2];
    const float* wq_b = (const float*)d_in[3];
    const float* wk_w = (const float*)d_in[4];
    const float* wk_b = (const float*)d_in[5];
    const float* wv_w = (const float*)d_in[6];
    const float* wv_b = (const float*)d_in[7];
    const float* wo_w = (const float*)d_in[8];
    const float* wo_b = (const float*)d_in[9];
    float* out = (float*)d_out;

    float *Qp, *Kp, *Vp, *Cp;
    cudaGetSymbolAddress((void**)&Qp, g_Q);
    cudaGetSymbolAddress((void**)&Kp, g_K);
    cudaGetSymbolAddress((void**)&Vp, g_V);
    cudaGetSymbolAddress((void**)&Cp, g_C);

    cudaFuncSetAttribute(gemm_qkv,
                         cudaFuncAttributeMaxDynamicSharedMemorySize, GSMEM);
    cudaFuncSetAttribute(gemm_single,
                         cudaFuncAttributeMaxDynamicSharedMemorySize, GSMEM);
    cudaFuncSetAttribute(flash_tc,
                         cudaFuncAttributeMaxDynamicSharedMemorySize, FSMEM);

    // fused Q/K/V projections
    gemm_qkv<<<dim3(12, MM / 128), 256, GSMEM>>>(
        x, wq_w, wq_b, Qp, wk_w, wk_b, Kp, wv_w, wv_b, Vp);

    // causal GQA flash attention
    flash_tc<<<dim3(SS / 128, HH, BB), 256, FSMEM>>>(Qp, Kp, Vp, Cp);

    // output projection
    gemm_single<<<dim3(EE / 128, MM / 128), 256, GSMEM>>>(Cp, wo_w, wo_b, out);
}

// round 7
// speedup vs baseline: 1.0984x; 1.0984x over previous
#include <cuda_runtime.h>
#include <cuda_bf16.h>
#include <cstdint>

// Problem constants
#define BB   2
#define SS   2048
#define EE   1024
#define HH   16
#define HKV  4
#define DD   64
#define KVE  (HKV * DD)   // 256
#define MM   (BB * SS)    // 4096

// Scratch (allocation-free rule: __device__ globals)
__device__ float g_Q[(size_t)MM * EE];     // tf32-bit Q
__device__ float g_K[(size_t)MM * KVE];    // tf32-bit K
__device__ float g_V[(size_t)MM * KVE];    // tf32-bit V
__device__ float g_C[(size_t)MM * EE];     // tf32-bit context
__device__ float g_xt[(size_t)MM * EE];    // tf32-bit x
__device__ float g_wqt[(size_t)EE * EE];   // tf32-bit weights
__device__ float g_wkt[(size_t)KVE * EE];
__device__ float g_wvt[(size_t)KVE * EE];
__device__ float g_wot[(size_t)EE * EE];

__device__ __forceinline__ uint32_t f2tf32(float x) {
    uint32_t u;
    asm("cvt.rna.tf32.f32 %0, %1;" : "=r"(u) : "f"(x));
    return u;
}
__device__ __forceinline__ void mma_tf32(float* c, const uint32_t* a,
                                         const uint32_t* b) {
    asm volatile(
        "mma.sync.aligned.m16n8k8.row.col.f32.tf32.tf32.f32 "
        "{%0,%1,%2,%3}, {%4,%5,%6,%7}, {%8,%9}, {%0,%1,%2,%3};"
        : "+f"(c[0]), "+f"(c[1]), "+f"(c[2]), "+f"(c[3])
        : "r"(a[0]), "r"(a[1]), "r"(a[2]), "r"(a[3]),
          "r"(b[0]), "r"(b[1]));
}
__device__ __forceinline__ void cp16(uint32_t d, const void* s) {
    asm volatile("cp.async.cg.shared.global [%0], [%1], 16;"
                 :: "r"(d), "l"(s) : "memory");
}
__device__ __forceinline__ void cp_commit() {
    asm volatile("cp.async.commit_group;" ::: "memory");
}
__device__ __forceinline__ void cp_wait0() {
    asm volatile("cp.async.wait_group 0;" ::: "memory");
}
__device__ __forceinline__ void cp_wait1() {
    asm volatile("cp.async.wait_group 1;" ::: "memory");
}
__device__ __forceinline__ uint32_t cvta_s(const void* p) {
    return (uint32_t)__cvta_generic_to_shared(p);
}

// ===========================================================================
// Prep: convert x + all weights to tf32 bit patterns (stored as float)
// ===========================================================================
#define NX  (MM * EE)            // 4194304
#define NWQ (EE * EE)            // 1048576
#define NWK (KVE * EE)           // 262144
#define NTOT (NX + NWQ + 2 * NWK + NWQ)   // 6815744

__global__ void __launch_bounds__(256)
prep_tf32(const float* __restrict__ x,
          const float* __restrict__ wq, const float* __restrict__ wk,
          const float* __restrict__ wv, const float* __restrict__ wo)
{
    const int nvec = NTOT / 4;
    for (int i = blockIdx.x * blockDim.x + threadIdx.x; i < nvec;
         i += gridDim.x * blockDim.x) {
        const int e = i * 4;
        const float* src;
        float* dst;
        int off;
        if (e < NX)                    { src = x;  dst = g_xt;  off = e; }
        else if (e < NX + NWQ)         { src = wq; dst = g_wqt; off = e - NX; }
        else if (e < NX + NWQ + NWK)   { src = wk; dst = g_wkt; off = e - NX - NWQ; }
        else if (e < NX + NWQ + 2*NWK) { src = wv; dst = g_wvt; off = e - NX - NWQ - NWK; }
        else                           { src = wo; dst = g_wot; off = e - NX - NWQ - 2*NWK; }
        float4 v = *(const float4*)(src + off);
        uint4 u;
        u.x = f2tf32(v.x); u.y = f2tf32(v.y);
        u.z = f2tf32(v.z); u.w = f2tf32(v.w);
        *(uint4*)(dst + off) = u;
    }
}

// ===========================================================================
// tf32 tensor-core GEMM core: inputs already tf32 bits, no cvt in hot loop.
// 3-stage cp.async ring, one barrier per k-iter.
// CVT_OUT: store tf32-converted output (for tensors consumed by later MMAs).
// ===========================================================================
#define GBK   32
#define GLDA  36
#define GBUF  (128 * GLDA)
#define GSTG  3
#define GSMEM (2 * GSTG * GBUF * 4)     // 110592 bytes

template <bool CVT_OUT>
__device__ __forceinline__ void gemm_core(
    const float* __restrict__ A, const float* __restrict__ W,
    const float* __restrict__ bias, float* __restrict__ C,
    int Nc, int row0)
{
    extern __shared__ float sm[];
    float* As = sm;
    float* Bs = sm + GSTG * GBUF;

    const int tid  = threadIdx.x;
    const int K    = EE;

    const int r    = tid >> 1;
    const int ksub = (tid & 1) * 16;
    const float* Ag = A + (size_t)(row0 + r) * K + ksub;
    const float* Wg = W + (size_t)r * K + ksub;
    const uint32_t Asd = cvta_s(As + r * GLDA + ksub);
    const uint32_t Bsd = cvta_s(Bs + r * GLDA + ksub);

    const int lane = tid & 31;
    const int wid  = tid >> 5;
    const int wm   = (wid & 1) * 64;
    const int wn   = (wid >> 1) * 32;
    const int g    = lane >> 2;
    const int tig  = lane & 3;

    float acc[4][4][4];
#pragma unroll
    for (int mt = 0; mt < 4; mt++)
#pragma unroll
        for (int nt = 0; nt < 4; nt++)
#pragma unroll
            for (int i = 0; i < 4; i++) acc[mt][nt][i] = 0.f;

#pragma unroll
    for (int s = 0; s < 2; s++) {
#pragma unroll
        for (int i = 0; i < 4; i++) {
            cp16(Asd + s * GBUF * 4 + i * 16, Ag + s * GBK + i * 4);
            cp16(Bsd + s * GBUF * 4 + i * 16, Wg + s * GBK + i * 4);
        }
        cp_commit();
    }

    const int NI = K / GBK;
    int bcur = 0, bpre = 2;
    for (int it = 0; it < NI; it++) {
        if (it + 1 < NI) cp_wait1(); else cp_wait0();
        __syncthreads();

        if (it + 2 < NI) {
            const float* a = Ag + (it + 2) * GBK;
            const float* w = Wg + (it + 2) * GBK;
            const uint32_t ad = Asd + bpre * GBUF * 4;
            const uint32_t bd = Bsd + bpre * GBUF * 4;
#pragma unroll
            for (int i = 0; i < 4; i++) {
                cp16(ad + i * 16, a + i * 4);
                cp16(bd + i * 16, w + i * 4);
            }
            cp_commit();
        }

        const uint32_t* Ab = (const uint32_t*)(As + bcur * GBUF);
        const uint32_t* Bb = (const uint32_t*)(Bs + bcur * GBUF);
#pragma unroll
        for (int ks = 0; ks < 4; ks++) {
            uint32_t a[4][4], b[4][2];
#pragma unroll
            for (int mt = 0; mt < 4; mt++) {
                const uint32_t* ap = Ab + (wm + mt * 16 + g) * GLDA + ks * 8 + tig;
                a[mt][0] = ap[0];
                a[mt][1] = ap[8 * GLDA];
                a[mt][2] = ap[4];
                a[mt][3] = ap[8 * GLDA + 4];
            }
#pragma unroll
            for (int nt = 0; nt < 4; nt++) {
                const uint32_t* bp = Bb + (wn + nt * 8 + g) * GLDA + ks * 8 + tig;
                b[nt][0] = bp[0];
                b[nt][1] = bp[4];
            }
#pragma unroll
            for (int mt = 0; mt < 4; mt++)
#pragma unroll
                for (int nt = 0; nt < 4; nt++)
                    mma_tf32(acc[mt][nt], a[mt], b[nt]);
        }

        bcur = (bcur + 1 == GSTG) ? 0 : bcur + 1;
        bpre = (bpre + 1 == GSTG) ? 0 : bpre + 1;
    }

    // epilogue: fused bias; optionally re-encode as tf32 bits
#pragma unroll
    for (int mt = 0; mt < 4; mt++) {
        const int rowa = row0 + wm + mt * 16 + g;
#pragma unroll
        for (int nt = 0; nt < 4; nt++) {
            const int cola = wn + nt * 8 + 2 * tig;
            const float2 bv = *(const float2*)(bias + cola);
            float s0 = acc[mt][nt][0] + bv.x;
            float s1 = acc[mt][nt][1] + bv.y;
            float s2 = acc[mt][nt][2] + bv.x;
            float s3 = acc[mt][nt][3] + bv.y;
            float2 v0, v1;
            if (CVT_OUT) {
                v0.x = __uint_as_float(f2tf32(s0));
                v0.y = __uint_as_float(f2tf32(s1));
                v1.x = __uint_as_float(f2tf32(s2));
                v1.y = __uint_as_float(f2tf32(s3));
            } else {
                v0.x = s0; v0.y = s1; v1.x = s2; v1.y = s3;
            }
            *(float2*)(C + (size_t)rowa * Nc + cola)       = v0;
            *(float2*)(C + (size_t)(rowa + 8) * Nc + cola) = v1;
        }
    }
}

// fused Q/K/V projection: tiles 0-7 -> Q, 8-9 -> K, 10-11 -> V
__global__ void __launch_bounds__(256, 2)
gemm_qkv(float* Qo, float* Ko, float* Vo,
         const float* __restrict__ bq, const float* __restrict__ bk,
         const float* __restrict__ bv)
{
    const int bx   = blockIdx.x;
    const int row0 = blockIdx.y * 128;
    const float *W, *bias;
    float* C;
    int Nc, c0;
    if (bx < 8)       { W = g_wqt; bias = bq; C = Qo; Nc = EE;  c0 = bx * 128; }
    else if (bx < 10) { W = g_wkt; bias = bk; C = Ko; Nc = KVE; c0 = (bx - 8) * 128; }
    else              { W = g_wvt; bias = bv; C = Vo; Nc = KVE; c0 = (bx - 10) * 128; }
    gemm_core<true>(g_xt, W + (size_t)c0 * EE, bias + c0, C + c0, Nc, row0);
}

__global__ void __launch_bounds__(256, 2)
gemm_single(const float* __restrict__ A, const float* __restrict__ bias,
            float* __restrict__ C)
{
    const int c0 = blockIdx.x * 128;
    gemm_core<false>(A, g_wot + (size_t)c0 * EE, bias + c0, C + c0, EE,
                     blockIdx.y * 128);
}

// ===========================================================================
// Tensor-core flash attention (causal, GQA), tf32 mma.sync.
// Q/K/V already tf32 bits -> no cvt on fragment loads.
// 2-stage cp.async K/V ring, one barrier per KV tile.
// ===========================================================================
#define PLD 68
#define KLD 68
#define VLD 72
#define FKB (64 * KLD)
#define FVB (64 * VLD)
#define FSMEM ((128 * PLD + 2 * FKB + 2 * FVB) * 4)   // 106496 bytes

__global__ void __launch_bounds__(256, 2)
flash_tc(const float* __restrict__ Q, const float* __restrict__ K,
         const float* __restrict__ V, float* __restrict__ O)
{
    extern __shared__ float fsm[];
    float* Ps = fsm;                 // [128][PLD]
    float* Kb = fsm + 128 * PLD;     // [2][64][KLD]
    float* Vb = Kb + 2 * FKB;        // [2][64][VLD]

    const int tid  = threadIdx.x;
    const int lane = tid & 31;
    const int wid  = tid >> 5;
    const int g    = lane >> 2;
    const int tig  = lane & 3;
    const int m0   = (gridDim.x - 1 - blockIdx.x) * 128;   // heavy-first
    const int h    = blockIdx.y;
    const int b    = blockIdx.z;
    const int kvh  = h >> 2;

    const int sr  = tid >> 2;
    const int sc4 = (tid & 3) * 16;
    const float* kgb = K + ((size_t)(b * SS + sr)) * KVE + kvh * DD + sc4;
    const float* vgb = V + ((size_t)(b * SS + sr)) * KVE + kvh * DD + sc4;
    const uint32_t kd0 = cvta_s(Kb + sr * KLD + sc4);
    const uint32_t vd0 = cvta_s(Vb + sr * VLD + sc4);

    // stage Q (x 0.125: exact power of two on tf32 bits)
    {
        const int r  = tid >> 1;
        const int c0 = (tid & 1) * 32;
        const float* qg = Q + ((size_t)(b * SS + m0 + r)) * EE + h * DD + c0;
        float* dst = Ps + r * PLD + c0;
#pragma unroll
        for (int i = 0; i < 8; i++) {
            float4 v = *(const float4*)(qg + i * 4);
            dst[i * 4 + 0] = v.x * 0.125f;
            dst[i * 4 + 1] = v.y * 0.125f;
            dst[i * 4 + 2] = v.z * 0.125f;
            dst[i * 4 + 3] = v.w * 0.125f;
        }
    }

    const int ntile = m0 / 64 + 2;

#pragma unroll
    for (int i = 0; i < 4; i++) {
        cp16(kd0 + i * 16, kgb + i * 4);
        cp16(vd0 + i * 16, vgb + i * 4);
    }
    cp_commit();
    __syncthreads();                 // Q visible

    uint32_t qa[8][4];
    {
        const uint32_t* base = (const uint32_t*)(Ps + (wid * 16 + g) * PLD);
#pragma unroll
        for (int ks = 0; ks < 8; ks++) {
            qa[ks][0] = base[ks * 8 + tig];
            qa[ks][1] = base[8 * PLD + ks * 8 + tig];
            qa[ks][2] = base[ks * 8 + tig + 4];
            qa[ks][3] = base[8 * PLD + ks * 8 + tig + 4];
        }
    }

    float oacc[8][4];
#pragma unroll
    for (int nt = 0; nt < 8; nt++)
#pragma unroll
        for (int i = 0; i < 4; i++) oacc[nt][i] = 0.f;
    float mrow[2] = { -1e30f, -1e30f };
    float lrow[2] = { 0.f, 0.f };

    const int r0 = m0 + wid * 16 + g;

    for (int t = 0; t < ntile; t++) {
        const int cb = t & 1;

        cp_wait0();
        __syncthreads();

        if (t + 1 < ntile) {
            const float* kg = kgb + (size_t)((t + 1) * 64) * KVE;
            const float* vg = vgb + (size_t)((t + 1) * 64) * KVE;
            const uint32_t kd = kd0 + (1 - cb) * FKB * 4;
            const uint32_t vd = vd0 + (1 - cb) * FVB * 4;
#pragma unroll
            for (int i = 0; i < 4; i++) {
                cp16(kd + i * 16, kg + i * 4);
                cp16(vd + i * 16, vg + i * 4);
            }
            cp_commit();
        }

        const int j0 = t * 64;
        const bool active = (j0 <= m0 + wid * 16 + 15);    // warp-uniform
        if (active) {
            const uint32_t* Kc = (const uint32_t*)(Kb + cb * FKB);
            const uint32_t* Vc = (const uint32_t*)(Vb + cb * FVB);

            // S = Q @ K^T
            float sc[8][4];
#pragma unroll
            for (int nt = 0; nt < 8; nt++)
#pragma unroll
                for (int i = 0; i < 4; i++) sc[nt][i] = 0.f;
#pragma unroll
            for (int ks = 0; ks < 8; ks++)
#pragma unroll
                for (int nt = 0; nt < 8; nt++) {
                    uint32_t bb[2];
                    const uint32_t* bp = Kc + (nt * 8 + g) * KLD + ks * 8 + tig;
                    bb[0] = bp[0];
                    bb[1] = bp[4];
                    mma_tf32(sc[nt], qa[ks], bb);
                }

            // causal mask (diagonal tiles only)
            if (j0 + 63 > r0) {
#pragma unroll
                for (int nt = 0; nt < 8; nt++) {
                    const int c = j0 + nt * 8 + 2 * tig;
                    if (c     > r0)     sc[nt][0] = -1e30f;
                    if (c + 1 > r0)     sc[nt][1] = -1e30f;
                    if (c     > r0 + 8) sc[nt][2] = -1e30f;
                    if (c + 1 > r0 + 8) sc[nt][3] = -1e30f;
                }
            }

            // row max (quad reduce)
            float tm0 = -1e30f, tm1 = -1e30f;
#pragma unroll
            for (int nt = 0; nt < 8; nt++) {
                tm0 = fmaxf(tm0, fmaxf(sc[nt][0], sc[nt][1]));
                tm1 = fmaxf(tm1, fmaxf(sc[nt][2], sc[nt][3]));
            }
            tm0 = fmaxf(tm0, __shfl_xor_sync(0xffffffffu, tm0, 1));
            tm0 = fmaxf(tm0, __shfl_xor_sync(0xffffffffu, tm0, 2));
            tm1 = fmaxf(tm1, __shfl_xor_sync(0xffffffffu, tm1, 1));
            tm1 = fmaxf(tm1, __shfl_xor_sync(0xffffffffu, tm1, 2));

            const float mn0 = fmaxf(mrow[0], tm0);
            const float mn1 = fmaxf(mrow[1], tm1);
            const float cr0 = __expf(mrow[0] - mn0);
            const float cr1 = __expf(mrow[1] - mn1);
            mrow[0] = mn0; mrow[1] = mn1;

            float ls0 = 0.f, ls1 = 0.f;
#pragma unroll
            for (int nt = 0; nt < 8; nt++) {
                sc[nt][0] = __expf(sc[nt][0] - mn0); ls0 += sc[nt][0];
                sc[nt][1] = __expf(sc[nt][1] - mn0); ls0 += sc[nt][1];
                sc[nt][2] = __expf(sc[nt][2] - mn1); ls1 += sc[nt][2];
                sc[nt][3] = __expf(sc[nt][3] - mn1); ls1 += sc[nt][3];
            }
            lrow[0] = lrow[0] * cr0 + ls0;
            lrow[1] = lrow[1] * cr1 + ls1;
#pragma unroll
            for (int nt = 0; nt < 8; nt++) {
                oacc[nt][0] *= cr0; oacc[nt][1] *= cr0;
                oacc[nt][2] *= cr1; oacc[nt][3] *= cr1;
            }

            // P -> smem (tf32 bits), warp-private rows
            uint32_t* pr = (uint32_t*)(Ps + (wid * 16 + g) * PLD);
#pragma unroll
            for (int nt = 0; nt < 8; nt++) {
                uint2 w0, w1;
                w0.x = f2tf32(sc[nt][0]); w0.y = f2tf32(sc[nt][1]);
                w1.x = f2tf32(sc[nt][2]); w1.y = f2tf32(sc[nt][3]);
                *(uint2*)(pr + nt * 8 + 2 * tig)           = w0;
                *(uint2*)(pr + 8 * PLD + nt * 8 + 2 * tig) = w1;
            }
            __syncwarp();

            // O += P @ V
#pragma unroll
            for (int ks = 0; ks < 8; ks++) {
                uint32_t pa[4];
                pa[0] = pr[ks * 8 + tig];
                pa[1] = pr[8 * PLD + ks * 8 + tig];
                pa[2] = pr[ks * 8 + tig + 4];
                pa[3] = pr[8 * PLD + ks * 8 + tig + 4];
#pragma unroll
                for (int nt = 0; nt < 8; nt++) {
                    uint32_t bb[2];
                    bb[0] = Vc[(ks * 8 + tig) * VLD + nt * 8 + g];
                    bb[1] = Vc[(ks * 8 + tig + 4) * VLD + nt * 8 + g];
                    mma_tf32(oacc[nt], pa, bb);
                }
            }
        }
    }

    // finalize: store context as tf32 bits (consumed by gemm_single MMA)
    lrow[0] += __shfl_xor_sync(0xffffffffu, lrow[0], 1);
    lrow[0] += __shfl_xor_sync(0xffffffffu, lrow[0], 2);
    lrow[1] += __shfl_xor_sync(0xffffffffu, lrow[1], 1);
    lrow[1] += __shfl_xor_sync(0xffffffffu, lrow[1], 2);
    const float inv0 = 1.f / lrow[0];
    const float inv1 = 1.f / lrow[1];

    float* og = O + ((size_t)(b * SS + r0)) * EE + h * DD;
#pragma unroll
    for (int nt = 0; nt < 8; nt++) {
        float2 v0, v1;
        v0.x = __uint_as_float(f2tf32(oacc[nt][0] * inv0));
        v0.y = __uint_as_float(f2tf32(oacc[nt][1] * inv0));
        v1.x = __uint_as_float(f2tf32(oacc[nt][2] * inv1));
        v1.y = __uint_as_float(f2tf32(oacc[nt][3] * inv1));
        *(float2*)(og + nt * 8 + 2 * tig)                  = v0;
        *(float2*)(og + (size_t)8 * EE + nt * 8 + 2 * tig) = v1;
    }
}

// ---------------------------------------------------------------------------
// Launch
// ---------------------------------------------------------------------------
extern "C" void kernel_launch(void* const* d_in, const int* in_sizes, int n_in,
                              void* d_out, int out_size)
{
    const float* x    = (const float*)d_in[0];
    // d_in[1] is the causal mask (triu, k=1) — applied analytically (j<=i).
    const float* wq_w = (const float*)d_in[2];
    const float* wq_b = (const float*)d_in[3];
    const float* wk_w = (const float*)d_in[4];
    const float* wk_b = (const float*)d_in[5];
    const float* wv_w = (const float*)d_in[6];
    const float* wv_b = (const float*)d_in[7];
    const float* wo_w = (const float*)d_in[8];
    const float* wo_b = (const float*)d_in[9];
    float* out = (float*)d_out;

    float *Qp, *Kp, *Vp, *Cp;
    cudaGetSymbolAddress((void**)&Qp, g_Q);
    cudaGetSymbolAddress((void**)&Kp, g_K);
    cudaGetSymbolAddress((void**)&Vp, g_V);
    cudaGetSymbolAddress((void**)&Cp, g_C);

    cudaFuncSetAttribute(gemm_qkv,
                         cudaFuncAttributeMaxDynamicSharedMemorySize, GSMEM);
    cudaFuncSetAttribute(gemm_single,
                         cudaFuncAttributeMaxDynamicSharedMemorySize, GSMEM);
    cudaFuncSetAttribute(flash_tc,
                         cudaFuncAttributeMaxDynamicSharedMemorySize, FSMEM);

    // convert x + weights to tf32 storage
    prep_tf32<<<1024, 256>>>(x, wq_w, wk_w, wv_w, wo_w);

    // fused Q/K/V projections (tf32 in, tf32 out)
    gemm_qkv<<<dim3(12, MM / 128), 256, GSMEM>>>(Qp, Kp, Vp, wq_b, wk_b, wv_b);

    // causal GQA flash attention (tf32 in, tf32 context out)
    flash_tc<<<dim3(SS / 128, HH, BB), 256, FSMEM>>>(Qp, Kp, Vp, Cp);

    // output projection (fp32 out)
    gemm_single<<<dim3(EE / 128, MM / 128), 256, GSMEM>>>(Cp, wo_b, out);
}

// round 8
// speedup vs baseline: 1.2207x; 1.1114x over previous
#include <cuda_runtime.h>
#include <cuda_bf16.h>
#include <cstdint>

// Problem constants
#define BB   2
#define SS   2048
#define EE   1024
#define HH   16
#define HKV  4
#define DD   64
#define KVE  (HKV * DD)   // 256
#define MM   (BB * SS)    // 4096

// Scratch (allocation-free rule: __device__ globals)
__device__ float g_Q[(size_t)MM * EE];     // tf32-bit Q
__device__ float g_K[(size_t)MM * KVE];    // tf32-bit K
__device__ float g_Vt[(size_t)KVE * MM];   // tf32-bit V, TRANSPOSED [d][pos]
__device__ float g_C[(size_t)MM * EE];     // tf32-bit context
__device__ float g_xt[(size_t)MM * EE];    // tf32-bit x
__device__ float g_wqt[(size_t)EE * EE];   // tf32-bit weights
__device__ float g_wkt[(size_t)KVE * EE];
__device__ float g_wvt[(size_t)KVE * EE];
__device__ float g_wot[(size_t)EE * EE];

__device__ __forceinline__ uint32_t f2tf32(float x) {
    uint32_t u;
    asm("cvt.rna.tf32.f32 %0, %1;" : "=r"(u) : "f"(x));
    return u;
}
__device__ __forceinline__ void mma_tf32(float* c, const uint32_t* a,
                                         const uint32_t* b) {
    asm volatile(
        "mma.sync.aligned.m16n8k8.row.col.f32.tf32.tf32.f32 "
        "{%0,%1,%2,%3}, {%4,%5,%6,%7}, {%8,%9}, {%0,%1,%2,%3};"
        : "+f"(c[0]), "+f"(c[1]), "+f"(c[2]), "+f"(c[3])
        : "r"(a[0]), "r"(a[1]), "r"(a[2]), "r"(a[3]),
          "r"(b[0]), "r"(b[1]));
}
__device__ __forceinline__ void ldsm_x4(uint32_t* r, uint32_t addr) {
    asm volatile("ldmatrix.sync.aligned.m8n8.x4.shared.b16 {%0,%1,%2,%3}, [%4];"
                 : "=r"(r[0]), "=r"(r[1]), "=r"(r[2]), "=r"(r[3])
                 : "r"(addr));
}
__device__ __forceinline__ void cp16(uint32_t d, const void* s) {
    asm volatile("cp.async.cg.shared.global [%0], [%1], 16;"
                 :: "r"(d), "l"(s) : "memory");
}
__device__ __forceinline__ void cp_commit() {
    asm volatile("cp.async.commit_group;" ::: "memory");
}
__device__ __forceinline__ void cp_wait0() {
    asm volatile("cp.async.wait_group 0;" ::: "memory");
}
__device__ __forceinline__ void cp_wait1() {
    asm volatile("cp.async.wait_group 1;" ::: "memory");
}
__device__ __forceinline__ uint32_t cvta_s(const void* p) {
    return (uint32_t)__cvta_generic_to_shared(p);
}

// ===========================================================================
// Prep: convert x + all weights to tf32 bit patterns (stored as float)
// ===========================================================================
#define NX  (MM * EE)
#define NWQ (EE * EE)
#define NWK (KVE * EE)
#define NTOT (NX + NWQ + 2 * NWK + NWQ)

__global__ void __launch_bounds__(256)
prep_tf32(const float* __restrict__ x,
          const float* __restrict__ wq, const float* __restrict__ wk,
          const float* __restrict__ wv, const float* __restrict__ wo)
{
    const int nvec = NTOT / 4;
    for (int i = blockIdx.x * blockDim.x + threadIdx.x; i < nvec;
         i += gridDim.x * blockDim.x) {
        const int e = i * 4;
        const float* src;
        float* dst;
        int off;
        if (e < NX)                    { src = x;  dst = g_xt;  off = e; }
        else if (e < NX + NWQ)         { src = wq; dst = g_wqt; off = e - NX; }
        else if (e < NX + NWQ + NWK)   { src = wk; dst = g_wkt; off = e - NX - NWQ; }
        else if (e < NX + NWQ + 2*NWK) { src = wv; dst = g_wvt; off = e - NX - NWQ - NWK; }
        else                           { src = wo; dst = g_wot; off = e - NX - NWQ - 2*NWK; }
        float4 v = *(const float4*)(src + off);
        uint4 u;
        u.x = f2tf32(v.x); u.y = f2tf32(v.y);
        u.z = f2tf32(v.z); u.w = f2tf32(v.w);
        *(uint4*)(dst + off) = u;
    }
}

// ===========================================================================
// tf32 tensor-core GEMM core: ldmatrix fragment loads, 3-stage cp.async ring.
// OUT: 0 = fp32 direct, 1 = tf32 bits, 2 = tf32 bits transposed (C[col][row])
// ===========================================================================
#define GBK   32
#define GLDA  36
#define GBUF  (128 * GLDA)
#define GSTG  3
#define GSMEM (2 * GSTG * GBUF * 4)     // 110592 bytes

template <int OUT>
__device__ __forceinline__ void gemm_core(
    const float* __restrict__ A, const float* __restrict__ W,
    const float* __restrict__ bias, float* __restrict__ C,
    int Nc, int row0)
{
    extern __shared__ float sm[];
    float* As = sm;
    float* Bs = sm + GSTG * GBUF;

    const int tid  = threadIdx.x;
    const int K    = EE;

    const int r    = tid >> 1;
    const int ksub = (tid & 1) * 16;
    const float* Ag = A + (size_t)(row0 + r) * K + ksub;
    const float* Wg = W + (size_t)r * K + ksub;
    const uint32_t Asd = cvta_s(As + r * GLDA + ksub);
    const uint32_t Bsd = cvta_s(Bs + r * GLDA + ksub);

    const int lane = tid & 31;
    const int wid  = tid >> 5;
    const int wm   = (wid & 1) * 64;
    const int wn   = (wid >> 1) * 32;
    const int g    = lane >> 2;
    const int tig  = lane & 3;

    // ldmatrix per-lane byte offsets within a buffer
    const uint32_t aoff =
        (uint32_t)(((wm + (lane & 15)) * GLDA + ((lane & 16) ? 4 : 0)) * 4);
    const uint32_t boff =
        (uint32_t)(((wn + (lane & 7) + ((lane & 16) ? 8 : 0)) * GLDA
                    + ((lane & 8) ? 4 : 0)) * 4);
    const uint32_t Abase0 = cvta_s(As);
    const uint32_t Bbase0 = cvta_s(Bs);

    float acc[4][4][4];
#pragma unroll
    for (int mt = 0; mt < 4; mt++)
#pragma unroll
        for (int nt = 0; nt < 4; nt++)
#pragma unroll
            for (int i = 0; i < 4; i++) acc[mt][nt][i] = 0.f;

#pragma unroll
    for (int s = 0; s < 2; s++) {
#pragma unroll
        for (int i = 0; i < 4; i++) {
            cp16(Asd + s * GBUF * 4 + i * 16, Ag + s * GBK + i * 4);
            cp16(Bsd + s * GBUF * 4 + i * 16, Wg + s * GBK + i * 4);
        }
        cp_commit();
    }

    const int NI = K / GBK;
    int bcur = 0, bpre = 2;
    for (int it = 0; it < NI; it++) {
        if (it + 1 < NI) cp_wait1(); else cp_wait0();
        __syncthreads();

        if (it + 2 < NI) {
            const float* a = Ag + (it + 2) * GBK;
            const float* w = Wg + (it + 2) * GBK;
            const uint32_t ad = Asd + bpre * GBUF * 4;
            const uint32_t bd = Bsd + bpre * GBUF * 4;
#pragma unroll
            for (int i = 0; i < 4; i++) {
                cp16(ad + i * 16, a + i * 4);
                cp16(bd + i * 16, w + i * 4);
            }
            cp_commit();
        }

        const uint32_t Ab = Abase0 + bcur * GBUF * 4 + aoff;
        const uint32_t Bb = Bbase0 + bcur * GBUF * 4 + boff;
#pragma unroll
        for (int ks = 0; ks < 4; ks++) {
            uint32_t a[4][4], b[2][4];
#pragma unroll
            for (int mt = 0; mt < 4; mt++)
                ldsm_x4(a[mt], Ab + (mt * 16 * GLDA + ks * 8) * 4);
#pragma unroll
            for (int np = 0; np < 2; np++)
                ldsm_x4(b[np], Bb + (np * 16 * GLDA + ks * 8) * 4);
#pragma unroll
            for (int mt = 0; mt < 4; mt++)
#pragma unroll
                for (int nt = 0; nt < 4; nt++)
                    mma_tf32(acc[mt][nt], a[mt], &b[nt >> 1][(nt & 1) * 2]);
        }

        bcur = (bcur + 1 == GSTG) ? 0 : bcur + 1;
        bpre = (bpre + 1 == GSTG) ? 0 : bpre + 1;
    }

#pragma unroll
    for (int mt = 0; mt < 4; mt++) {
        const int rowa = row0 + wm + mt * 16 + g;
#pragma unroll
        for (int nt = 0; nt < 4; nt++) {
            const int cola = wn + nt * 8 + 2 * tig;
            const float2 bv = *(const float2*)(bias + cola);
            float s0 = acc[mt][nt][0] + bv.x;
            float s1 = acc[mt][nt][1] + bv.y;
            float s2 = acc[mt][nt][2] + bv.x;
            float s3 = acc[mt][nt][3] + bv.y;
            if (OUT == 2) {        // transposed tf32 store: C[col * MM + row]
                C[(size_t)cola * MM + rowa]           = __uint_as_float(f2tf32(s0));
                C[(size_t)(cola + 1) * MM + rowa]     = __uint_as_float(f2tf32(s1));
                C[(size_t)cola * MM + rowa + 8]       = __uint_as_float(f2tf32(s2));
                C[(size_t)(cola + 1) * MM + rowa + 8] = __uint_as_float(f2tf32(s3));
            } else {
                float2 v0, v1;
                if (OUT == 1) {
                    v0.x = __uint_as_float(f2tf32(s0));
                    v0.y = __uint_as_float(f2tf32(s1));
                    v1.x = __uint_as_float(f2tf32(s2));
                    v1.y = __uint_as_float(f2tf32(s3));
                } else {
                    v0.x = s0; v0.y = s1; v1.x = s2; v1.y = s3;
                }
                *(float2*)(C + (size_t)rowa * Nc + cola)       = v0;
                *(float2*)(C + (size_t)(rowa + 8) * Nc + cola) = v1;
            }
        }
    }
}

// fused Q/K/V projection: tiles 0-7 -> Q, 8-9 -> K, 10-11 -> V(transposed)
__global__ void __launch_bounds__(256, 2)
gemm_qkv(float* Qo, float* Ko, float* Vto,
         const float* __restrict__ bq, const float* __restrict__ bk,
         const float* __restrict__ bv)
{
    const int bx   = blockIdx.x;
    const int row0 = blockIdx.y * 128;
    if (bx < 8) {
        const int c0 = bx * 128;
        gemm_core<1>(g_xt, g_wqt + (size_t)c0 * EE, bq + c0, Qo + c0, EE, row0);
    } else if (bx < 10) {
        const int c0 = (bx - 8) * 128;
        gemm_core<1>(g_xt, g_wkt + (size_t)c0 * EE, bk + c0, Ko + c0, KVE, row0);
    } else {
        const int c0 = (bx - 10) * 128;
        gemm_core<2>(g_xt, g_wvt + (size_t)c0 * EE, bv + c0,
                     Vto + (size_t)c0 * MM, KVE, row0);
    }
}

__global__ void __launch_bounds__(256, 2)
gemm_single(const float* __restrict__ A, const float* __restrict__ bias,
            float* __restrict__ C)
{
    const int c0 = blockIdx.x * 128;
    gemm_core<0>(A, g_wot + (size_t)c0 * EE, bias + c0, C + c0, EE,
                 blockIdx.y * 128);
}

// ===========================================================================
// Tensor-core flash attention (causal, GQA), tf32 mma.sync + ldmatrix.
// K smem [kv][d]; V smem [d][kv] (from transposed g_Vt); P smem [q][kv-chunk].
// 2-stage cp.async ring, one barrier per KV tile.
// ===========================================================================
#define PLD 68
#define KLD 68
#define VLD 68
#define FKB (64 * KLD)
#define FVB (64 * VLD)
#define FSMEM ((128 * PLD + 2 * FKB + 2 * FVB) * 4)   // 104448 bytes

__global__ void __launch_bounds__(256, 2)
flash_tc(const float* __restrict__ Q, const float* __restrict__ K,
         const float* __restrict__ Vt, float* __restrict__ O)
{
    extern __shared__ float fsm[];
    float* Ps = fsm;                 // [128][PLD]
    float* Kb = fsm + 128 * PLD;     // [2][64][KLD]  rows = kv pos
    float* Vb = Kb + 2 * FKB;        // [2][64][VLD]  rows = d

    const int tid  = threadIdx.x;
    const int lane = tid & 31;
    const int wid  = tid >> 5;
    const int g    = lane >> 2;
    const int tig  = lane & 3;
    const int m0   = (gridDim.x - 1 - blockIdx.x) * 128;   // heavy-first
    const int h    = blockIdx.y;
    const int b    = blockIdx.z;
    const int kvh  = h >> 2;

    const int sr  = tid >> 2;
    const int sc4 = (tid & 3) * 16;
    const float* kgb = K + ((size_t)(b * SS + sr)) * KVE + kvh * DD + sc4;
    const float* vgb = Vt + ((size_t)(kvh * DD + sr)) * MM + b * SS + sc4;
    const uint32_t kd0 = cvta_s(Kb + sr * KLD + sc4);
    const uint32_t vd0 = cvta_s(Vb + sr * VLD + sc4);

    // ldmatrix per-lane byte offsets
    const uint32_t koff =
        (uint32_t)((((lane & 7) + ((lane & 16) ? 8 : 0)) * KLD
                    + ((lane & 8) ? 4 : 0)) * 4);
    const uint32_t voff =
        (uint32_t)((((lane & 7) + ((lane & 16) ? 8 : 0)) * VLD
                    + ((lane & 8) ? 4 : 0)) * 4);
    const uint32_t poff =
        (uint32_t)(((wid * 16 + (lane & 15)) * PLD + ((lane & 16) ? 4 : 0)) * 4);
    const uint32_t Pbase = cvta_s(Ps);
    const uint32_t Kbase0 = cvta_s(Kb);
    const uint32_t Vbase0 = cvta_s(Vb);

    // stage Q (x 0.125: exact power of two on tf32 bits)
    {
        const int r  = tid >> 1;
        const int c0 = (tid & 1) * 32;
        const float* qg = Q + ((size_t)(b * SS + m0 + r)) * EE + h * DD + c0;
        float* dst = Ps + r * PLD + c0;
#pragma unroll
        for (int i = 0; i < 8; i++) {
            float4 v = *(const float4*)(qg + i * 4);
            dst[i * 4 + 0] = v.x * 0.125f;
            dst[i * 4 + 1] = v.y * 0.125f;
            dst[i * 4 + 2] = v.z * 0.125f;
            dst[i * 4 + 3] = v.w * 0.125f;
        }
    }

    const int ntile = m0 / 64 + 2;

#pragma unroll
    for (int i = 0; i < 4; i++) {
        cp16(kd0 + i * 16, kgb + i * 4);
        cp16(vd0 + i * 16, vgb + i * 4);
    }
    cp_commit();
    __syncthreads();                 // Q visible

    uint32_t qa[8][4];
    {
        const uint32_t* base = (const uint32_t*)(Ps + (wid * 16 + g) * PLD);
#pragma unroll
        for (int ks = 0; ks < 8; ks++) {
            qa[ks][0] = base[ks * 8 + tig];
            qa[ks][1] = base[8 * PLD + ks * 8 + tig];
            qa[ks][2] = base[ks * 8 + tig + 4];
            qa[ks][3] = base[8 * PLD + ks * 8 + tig + 4];
        }
    }

    float oacc[8][4];
#pragma unroll
    for (int nt = 0; nt < 8; nt++)
#pragma unroll
        for (int i = 0; i < 4; i++) oacc[nt][i] = 0.f;
    float mrow[2] = { -1e30f, -1e30f };
    float lrow[2] = { 0.f, 0.f };

    const int r0 = m0 + wid * 16 + g;

    for (int t = 0; t < ntile; t++) {
        const int cb = t & 1;

        cp_wait0();
        __syncthreads();

        if (t + 1 < ntile) {
            const float* kg = kgb + (size_t)((t + 1) * 64) * KVE;
            const float* vg = vgb + (t + 1) * 64;
            const uint32_t kd = kd0 + (1 - cb) * FKB * 4;
            const uint32_t vd = vd0 + (1 - cb) * FVB * 4;
#pragma unroll
            for (int i = 0; i < 4; i++) {
                cp16(kd + i * 16, kg + i * 4);
                cp16(vd + i * 16, vg + i * 4);
            }
            cp_commit();
        }

        const int j0 = t * 64;
        const bool active = (j0 <= m0 + wid * 16 + 15);    // warp-uniform
        if (active) {
            const uint32_t Kc = Kbase0 + cb * FKB * 4 + koff;
            const uint32_t Vc = Vbase0 + cb * FVB * 4 + voff;

            // S = Q @ K^T
            float sc[8][4];
#pragma unroll
            for (int nt = 0; nt < 8; nt++)
#pragma unroll
                for (int i = 0; i < 4; i++) sc[nt][i] = 0.f;
#pragma unroll
            for (int ks = 0; ks < 8; ks++) {
                uint32_t kb[4][4];
#pragma unroll
                for (int np = 0; np < 4; np++)
                    ldsm_x4(kb[np], Kc + (np * 16 * KLD + ks * 8) * 4);
#pragma unroll
                for (int nt = 0; nt < 8; nt++)
                    mma_tf32(sc[nt], qa[ks], &kb[nt >> 1][(nt & 1) * 2]);
            }

            // causal mask (diagonal tiles only)
            if (j0 + 63 > r0) {
#pragma unroll
                for (int nt = 0; nt < 8; nt++) {
                    const int c = j0 + nt * 8 + 2 * tig;
                    if (c     > r0)     sc[nt][0] = -1e30f;
                    if (c + 1 > r0)     sc[nt][1] = -1e30f;
                    if (c     > r0 + 8) sc[nt][2] = -1e30f;
                    if (c + 1 > r0 + 8) sc[nt][3] = -1e30f;
                }
            }

            // row max (quad reduce)
            float tm0 = -1e30f, tm1 = -1e30f;
#pragma unroll
            for (int nt = 0; nt < 8; nt++) {
                tm0 = fmaxf(tm0, fmaxf(sc[nt][0], sc[nt][1]));
                tm1 = fmaxf(tm1, fmaxf(sc[nt][2], sc[nt][3]));
            }
            tm0 = fmaxf(tm0, __shfl_xor_sync(0xffffffffu, tm0, 1));
            tm0 = fmaxf(tm0, __shfl_xor_sync(0xffffffffu, tm0, 2));
            tm1 = fmaxf(tm1, __shfl_xor_sync(0xffffffffu, tm1, 1));
            tm1 = fmaxf(tm1, __shfl_xor_sync(0xffffffffu, tm1, 2));

            const float mn0 = fmaxf(mrow[0], tm0);
            const float mn1 = fmaxf(mrow[1], tm1);
            const float cr0 = __expf(mrow[0] - mn0);
            const float cr1 = __expf(mrow[1] - mn1);
            mrow[0] = mn0; mrow[1] = mn1;

            float ls0 = 0.f, ls1 = 0.f;
#pragma unroll
            for (int nt = 0; nt < 8; nt++) {
                sc[nt][0] = __expf(sc[nt][0] - mn0); ls0 += sc[nt][0];
                sc[nt][1] = __expf(sc[nt][1] - mn0); ls0 += sc[nt][1];
                sc[nt][2] = __expf(sc[nt][2] - mn1); ls1 += sc[nt][2];
                sc[nt][3] = __expf(sc[nt][3] - mn1); ls1 += sc[nt][3];
            }
            lrow[0] = lrow[0] * cr0 + ls0;
            lrow[1] = lrow[1] * cr1 + ls1;
#pragma unroll
            for (int nt = 0; nt < 8; nt++) {
                oacc[nt][0] *= cr0; oacc[nt][1] *= cr0;
                oacc[nt][2] *= cr1; oacc[nt][3] *= cr1;
            }

            // P -> smem (tf32 bits), warp-private rows
            uint32_t* pr = (uint32_t*)(Ps + (wid * 16 + g) * PLD);
#pragma unroll
            for (int nt = 0; nt < 8; nt++) {
                uint2 w0, w1;
                w0.x = f2tf32(sc[nt][0]); w0.y = f2tf32(sc[nt][1]);
                w1.x = f2tf32(sc[nt][2]); w1.y = f2tf32(sc[nt][3]);
                *(uint2*)(pr + nt * 8 + 2 * tig)           = w0;
                *(uint2*)(pr + 8 * PLD + nt * 8 + 2 * tig) = w1;
            }
            __syncwarp();

            // O += P @ V  (P and V fragments via ldmatrix)
#pragma unroll
            for (int ks = 0; ks < 8; ks++) {
                uint32_t pa[4], vb[4][4];
                ldsm_x4(pa, Pbase + poff + ks * 8 * 4);
#pragma unroll
                for (int np = 0; np < 4; np++)
                    ldsm_x4(vb[np], Vc + (np * 16 * VLD + ks * 8) * 4);
#pragma unroll
                for (int nt = 0; nt < 8; nt++)
                    mma_tf32(oacc[nt], pa, &vb[nt >> 1][(nt & 1) * 2]);
            }
        }
    }

    // finalize: store context as tf32 bits (consumed by gemm_single MMA)
    lrow[0] += __shfl_xor_sync(0xffffffffu, lrow[0], 1);
    lrow[0] += __shfl_xor_sync(0xffffffffu, lrow[0], 2);
    lrow[1] += __shfl_xor_sync(0xffffffffu, lrow[1], 1);
    lrow[1] += __shfl_xor_sync(0xffffffffu, lrow[1], 2);
    const float inv0 = 1.f / lrow[0];
    const float inv1 = 1.f / lrow[1];

    float* og = O + ((size_t)(b * SS + r0)) * EE + h * DD;
#pragma unroll
    for (int nt = 0; nt < 8; nt++) {
        float2 v0, v1;
        v0.x = __uint_as_float(f2tf32(oacc[nt][0] * inv0));
        v0.y = __uint_as_float(f2tf32(oacc[nt][1] * inv0));
        v1.x = __uint_as_float(f2tf32(oacc[nt][2] * inv1));
        v1.y = __uint_as_float(f2tf32(oacc[nt][3] * inv1));
        *(float2*)(og + nt * 8 + 2 * tig)                  = v0;
        *(float2*)(og + (size_t)8 * EE + nt * 8 + 2 * tig) = v1;
    }
}

// ---------------------------------------------------------------------------
// Launch
// ---------------------------------------------------------------------------
extern "C" void kernel_launch(void* const* d_in, const int* in_sizes, int n_in,
                              void* d_out, int out_size)
{
    const float* x    = (const float*)d_in[0];
    // d_in[1] is the causal mask (triu, k=1) — applied analytically (j<=i).
    const float* wq_w = (const float*)d_in[2];
    const float* wq_b = (const float*)d_in[3];
    const float* wk_w = (const float*)d_in[4];
    const float* wk_b = (const float*)d_in[5];
    const float* wv_w = (const float*)d_in[6];
    const float* wv_b = (const float*)d_in[7];
    const float* wo_w = (const float*)d_in[8];
    const float* wo_b = (const float*)d_in[9];
    float* out = (float*)d_out;

    float *Qp, *Kp, *Vtp, *Cp;
    cudaGetSymbolAddress((void**)&Qp, g_Q);
    cudaGetSymbolAddress((void**)&Kp, g_K);
    cudaGetSymbolAddress((void**)&Vtp, g_Vt);
    cudaGetSymbolAddress((void**)&Cp, g_C);

    cudaFuncSetAttribute(gemm_qkv,
                         cudaFuncAttributeMaxDynamicSharedMemorySize, GSMEM);
    cudaFuncSetAttribute(gemm_single,
                         cudaFuncAttributeMaxDynamicSharedMemorySize, GSMEM);
    cudaFuncSetAttribute(flash_tc,
                         cudaFuncAttributeMaxDynamicSharedMemorySize, FSMEM);

    // convert x + weights to tf32 storage
    prep_tf32<<<1024, 256>>>(x, wq_w, wk_w, wv_w, wo_w);

    // fused Q/K/V projections (V written transposed)
    gemm_qkv<<<dim3(12, MM / 128), 256, GSMEM>>>(Qp, Kp, Vtp, wq_b, wk_b, wv_b);

    // causal GQA flash attention
    flash_tc<<<dim3(SS / 128, HH, BB), 256, FSMEM>>>(Qp, Kp, Vtp, Cp);

    // output projection
    gemm_single<<<dim3(EE / 128, MM / 128), 256, GSMEM>>>(Cp, wo_b, out);
}